// round 3
// baseline (speedup 1.0000x reference)
#include <cuda_runtime.h>
#include <cstdint>
#include <cstddef>

// ---------------------------------------------------------------------------
// Covariance:  cov[b] = (X^T X)/N - mu mu^T, packed upper triangle.
// X: [64, 4096, 256] f32 -> out: [64, 32896] f32
// Plain sm_100 target (no tcgen05): Ampere-style mma.sync m16n8k8 TF32 SYRK.
// One CTA = (batch, m-slab of 128 rows) x all 256 cols. 128 CTAs, 256 thr.
// ---------------------------------------------------------------------------

static constexpr int BATCH  = 64;
static constexpr int NPTS   = 4096;
static constexpr int DIM    = 256;
static constexpr int TRI    = DIM * (DIM + 1) / 2;   // 32896
static constexpr int KC     = 32;                    // K per chunk
static constexpr int NCHUNK = NPTS / KC;             // 128
static constexpr int SROW   = 264;                   // smem floats per k-row (264%32==8)
static constexpr int STAGE_F = KC * SROW;            // 8448 floats / 33792 B
// smem: buf[2][STAGE_F] | psum[4*256] | csum[256]
static constexpr int SMEM_FLOATS = 2 * STAGE_F + 4 * 256 + 256;
static constexpr int SMEM_BYTES  = SMEM_FLOATS * 4;  // 72704

#define MMA_TF32(ac, A, b0, b1)                                                 \
    asm volatile(                                                               \
        "mma.sync.aligned.m16n8k8.row.col.f32.tf32.tf32.f32 "                   \
        "{%0,%1,%2,%3}, {%4,%5,%6,%7}, {%8,%9}, {%0,%1,%2,%3};"                 \
        : "+f"((ac)[0]), "+f"((ac)[1]), "+f"((ac)[2]), "+f"((ac)[3])            \
        : "r"((A)[0]), "r"((A)[1]), "r"((A)[2]), "r"((A)[3]),                   \
          "r"(b0), "r"(b1))

static __device__ __forceinline__ uint32_t cvt_rna_tf32(float v) {
    uint32_t r;
    asm("cvt.rna.tf32.f32 %0, %1;" : "=r"(r) : "f"(v));
    return r;
}

__global__ void __launch_bounds__(256, 1)
cov_mma_kernel(const float* __restrict__ X, float* __restrict__ out)
{
    extern __shared__ float sm[];
    float* buf0 = sm;
    float* buf1 = sm + STAGE_F;
    float* psum = sm + 2 * STAGE_F;        // [4][256]
    float* csum = psum + 4 * 256;          // [256]

    const int tid   = threadIdx.x;
    const int lane  = tid & 31;
    const int wid   = tid >> 5;
    const int b     = blockIdx.x >> 1;
    const int mtile = blockIdx.x & 1;
    const int warpM = wid >> 2;            // 0..1
    const int warpN = wid & 3;             // 0..3
    const int g     = lane >> 2;           // groupID 0..7
    const int tig   = lane & 3;            // thread-in-group 0..3

    // global staging: thread t owns float4 lanes t, t+256, ... within a chunk
    const float4* gp =
        reinterpret_cast<const float4*>(X + (size_t)b * NPTS * DIM) + tid;
    const int dq    = (tid & 63) * 4;      // fixed d-quad for this thread
    const int krow0 = tid >> 6;            // 0..3; rows krow0 + 4j

    float acc[4][8][4] = {};               // [mfrag][nfrag][c-reg]
    float s4[4] = {0.f, 0.f, 0.f, 0.f};    // partial column sums (d-quad)

    float4 v[8];

    // ---- prologue: stage chunk 0 ----
#pragma unroll
    for (int j = 0; j < 8; ++j) v[j] = gp[j * 256];
#pragma unroll
    for (int j = 0; j < 8; ++j) {
        uint32_t r0 = cvt_rna_tf32(v[j].x), r1 = cvt_rna_tf32(v[j].y);
        uint32_t r2 = cvt_rna_tf32(v[j].z), r3 = cvt_rna_tf32(v[j].w);
        s4[0] += __uint_as_float(r0); s4[1] += __uint_as_float(r1);
        s4[2] += __uint_as_float(r2); s4[3] += __uint_as_float(r3);
        *reinterpret_cast<float4*>(&buf0[(krow0 + 4 * j) * SROW + dq]) =
            make_float4(__uint_as_float(r0), __uint_as_float(r1),
                        __uint_as_float(r2), __uint_as_float(r3));
    }
    __syncthreads();

    const int am0 = mtile * 128 + warpM * 64;   // A d-base for this warp
    const int bn0 = warpN * 64;                 // B e-base for this warp

#pragma unroll 1
    for (int c = 0; c < NCHUNK; ++c) {
        // issue global loads for next chunk early (overlap with MMA)
        if (c + 1 < NCHUNK) {
#pragma unroll
            for (int j = 0; j < 8; ++j)
                v[j] = gp[(c + 1) * 2048 + j * 256];
        }

        const uint32_t* cur =
            reinterpret_cast<const uint32_t*>((c & 1) ? buf1 : buf0);

#pragma unroll
        for (int ks = 0; ks < 4; ++ks) {
            const int k0 = ks * 8;
            uint32_t af[4][4];
#pragma unroll
            for (int mf = 0; mf < 4; ++mf) {
                const int m0 = am0 + mf * 16 + g;
                af[mf][0] = cur[(k0 + tig)     * SROW + m0];
                af[mf][1] = cur[(k0 + tig)     * SROW + m0 + 8];
                af[mf][2] = cur[(k0 + tig + 4) * SROW + m0];
                af[mf][3] = cur[(k0 + tig + 4) * SROW + m0 + 8];
            }
            uint32_t bf[8][2];
#pragma unroll
            for (int nf = 0; nf < 8; ++nf) {
                const int n0 = bn0 + nf * 8 + g;
                bf[nf][0] = cur[(k0 + tig)     * SROW + n0];
                bf[nf][1] = cur[(k0 + tig + 4) * SROW + n0];
            }
#pragma unroll
            for (int mf = 0; mf < 4; ++mf)
#pragma unroll
                for (int nf = 0; nf < 8; ++nf)
                    MMA_TF32(acc[mf][nf], af[mf], bf[nf][0], bf[nf][1]);
        }

        // stage next chunk into the other buffer
        if (c + 1 < NCHUNK) {
            float* nxt = (c & 1) ? buf0 : buf1;
#pragma unroll
            for (int j = 0; j < 8; ++j) {
                uint32_t r0 = cvt_rna_tf32(v[j].x), r1 = cvt_rna_tf32(v[j].y);
                uint32_t r2 = cvt_rna_tf32(v[j].z), r3 = cvt_rna_tf32(v[j].w);
                s4[0] += __uint_as_float(r0); s4[1] += __uint_as_float(r1);
                s4[2] += __uint_as_float(r2); s4[3] += __uint_as_float(r3);
                *reinterpret_cast<float4*>(&nxt[(krow0 + 4 * j) * SROW + dq]) =
                    make_float4(__uint_as_float(r0), __uint_as_float(r1),
                                __uint_as_float(r2), __uint_as_float(r3));
            }
        }
        __syncthreads();
    }

    // ---- column-sum reduction ----
    psum[(tid >> 6) * 256 + (tid & 63) * 4 + 0] = s4[0];
    psum[(tid >> 6) * 256 + (tid & 63) * 4 + 1] = s4[1];
    psum[(tid >> 6) * 256 + (tid & 63) * 4 + 2] = s4[2];
    psum[(tid >> 6) * 256 + (tid & 63) * 4 + 3] = s4[3];
    __syncthreads();
    csum[tid] = psum[tid] + psum[256 + tid] + psum[512 + tid] + psum[768 + tid];
    __syncthreads();

    // ---- epilogue: cov = acc/N - mu_d mu_e, packed upper triangle ----
    const float invN = 1.0f / (float)NPTS;
    const size_t outb = (size_t)b * TRI;

#pragma unroll
    for (int mf = 0; mf < 4; ++mf) {
#pragma unroll
        for (int nf = 0; nf < 8; ++nf) {
            const int d0 = am0 + mf * 16 + g;
            const int e0 = bn0 + nf * 8 + 2 * tig;
#pragma unroll
            for (int cc = 0; cc < 4; ++cc) {
                const int d = d0 + (cc >> 1) * 8;
                const int e = e0 + (cc & 1);
                if (e >= d) {
                    const float mu_d = csum[d] * invN;
                    const float mu_e = csum[e] * invN;
                    const int idx = d * DIM - (d * (d - 1)) / 2 - d + e;
                    out[outb + (size_t)idx] =
                        acc[mf][nf][cc] * invN - mu_d * mu_e;
                }
            }
        }
    }
}

extern "C" void kernel_launch(void* const* d_in, const int* in_sizes, int n_in,
                              void* d_out, int out_size)
{
    const float* X = (const float*)d_in[0];
    float* out = (float*)d_out;
    cudaFuncSetAttribute(cov_mma_kernel,
                         cudaFuncAttributeMaxDynamicSharedMemorySize,
                         SMEM_BYTES);
    cov_mma_kernel<<<BATCH * 2, 256, SMEM_BYTES>>>(X, out);
}